// round 4
// baseline (speedup 1.0000x reference)
#include <cuda_runtime.h>
#include <math.h>
#include <stdint.h>

#define V_N 50000
#define E_N 800000

__device__ int    g_hist[V_N];
__device__ int    g_start[V_N + 1];
__device__ int    g_cursor[V_N];
__device__ int    g_src[E_N];
__device__ float4 g_trigA[E_N];   // (cos a, sin a, cos 2a, sin 2a)
__device__ float4 g_trigT[E_N];   // (cos t, sin t, cos 2t, sin 2t)
__device__ float  g_S[(size_t)V_N * 384];   // [S(320) | x(64)] per vertex

// ---------------- helpers ----------------
__device__ __forceinline__ uint32_t pack_bf16(float e0, float e1) {
    uint32_t r;
    asm("cvt.rn.bf16x2.f32 %0, %1, %2;" : "=r"(r) : "f"(e1), "f"(e0));
    return r;
}

__device__ __forceinline__ void mma_bf16(float* d, const uint32_t* a, const uint32_t* b) {
    asm volatile(
        "mma.sync.aligned.m16n8k16.row.col.f32.bf16.bf16.f32 "
        "{%0,%1,%2,%3}, {%4,%5,%6,%7}, {%8,%9}, {%0,%1,%2,%3};"
        : "+f"(d[0]), "+f"(d[1]), "+f"(d[2]), "+f"(d[3])
        : "r"(a[0]), "r"(a[1]), "r"(a[2]), "r"(a[3]), "r"(b[0]), "r"(b[1]));
}

// ---------------- sort pipeline ----------------
__global__ void zero_hist_kernel() {
    int i = blockIdx.x * blockDim.x + threadIdx.x;
    if (i < V_N) g_hist[i] = 0;
}

__global__ void hist_kernel(const int* __restrict__ ei) {
    int e = blockIdx.x * blockDim.x + threadIdx.x;
    if (e < E_N) atomicAdd(&g_hist[ei[E_N + e]], 1);
}

__global__ void scan_kernel() {
    __shared__ int sums[256];
    __shared__ int offs[256];
    const int t = threadIdx.x;
    const int base = t * 196;                 // 256*196 = 50176 >= V_N
    int s = 0;
    for (int i = 0; i < 196; ++i) {
        int idx = base + i;
        if (idx < V_N) s += g_hist[idx];
    }
    sums[t] = s;
    __syncthreads();
    if (t == 0) {
        int acc = 0;
        for (int i = 0; i < 256; ++i) { offs[i] = acc; acc += sums[i]; }
    }
    __syncthreads();
    int run = offs[t];
    for (int i = 0; i < 196; ++i) {
        int idx = base + i;
        if (idx < V_N) {
            g_start[idx]  = run;
            g_cursor[idx] = run;
            run += g_hist[idx];
        }
    }
    if (t == 255) g_start[V_N] = E_N;
}

__global__ void scatter_kernel(const int* __restrict__ ei,
                               const float* __restrict__ angles,
                               const float* __restrict__ trans) {
    int e = blockIdx.x * blockDim.x + threadIdx.x;
    if (e >= E_N) return;
    int tgt = ei[E_N + e];
    int pos = atomicAdd(&g_cursor[tgt], 1);
    g_src[pos] = ei[e];
    float sa, ca, st, ct;
    __sincosf(angles[e], &sa, &ca);
    __sincosf(trans[e],  &st, &ct);
    g_trigA[pos] = make_float4(ca, sa, fmaf(2.f * ca, ca, -1.f), 2.f * sa * ca);
    g_trigT[pos] = make_float4(ct, st, fmaf(2.f * ct, ct, -1.f), 2.f * st * ct);
}

// ---------------- per-vertex S accumulation ----------------
// One warp per vertex. Lane l owns channels (2l, 2l+1):
// lanes 0..7 scalars, 8..23 order-1 pairs, 24..31 order-2 pairs.
__global__ __launch_bounds__(256) void accum_kernel(const float* __restrict__ x) {
    const int lane = threadIdx.x & 31;
    const int gw   = (blockIdx.x * blockDim.x + threadIdx.x) >> 5;
    const int nw   = (gridDim.x * blockDim.x) >> 5;

    for (int v = gw; v < V_N; v += nw) {
        const int jb = g_start[v];
        const int je = g_start[v + 1];
        float2 S[5];
#pragma unroll
        for (int b = 0; b < 5; ++b) S[b] = make_float2(0.f, 0.f);

        int j = jb;
        for (; j + 2 <= je; j += 2) {
            const int s0 = g_src[j], s1 = g_src[j + 1];
            const float4 A0 = g_trigA[j],   A1 = g_trigA[j + 1];
            const float4 T0 = g_trigT[j],   T1 = g_trigT[j + 1];
            float2 f0 = *reinterpret_cast<const float2*>(x + (size_t)s0 * 64 + 2 * lane);
            float2 f1 = *reinterpret_cast<const float2*>(x + (size_t)s1 * 64 + 2 * lane);
            if (lane >= 8) {
                float cr0 = (lane < 24) ? T0.x : T0.z, sr0 = (lane < 24) ? T0.y : T0.w;
                float cr1 = (lane < 24) ? T1.x : T1.z, sr1 = (lane < 24) ? T1.y : T1.w;
                float a0 = cr0 * f0.x - sr0 * f0.y, b0 = sr0 * f0.x + cr0 * f0.y;
                float a1 = cr1 * f1.x - sr1 * f1.y, b1 = sr1 * f1.x + cr1 * f1.y;
                f0.x = a0; f0.y = b0; f1.x = a1; f1.y = b1;
            }
            S[0].x += f0.x + f1.x;            S[0].y += f0.y + f1.y;
            S[1].x += A0.x * f0.x + A1.x * f1.x;  S[1].y += A0.x * f0.y + A1.x * f1.y;
            S[2].x += A0.y * f0.x + A1.y * f1.x;  S[2].y += A0.y * f0.y + A1.y * f1.y;
            S[3].x += A0.z * f0.x + A1.z * f1.x;  S[3].y += A0.z * f0.y + A1.z * f1.y;
            S[4].x += A0.w * f0.x + A1.w * f1.x;  S[4].y += A0.w * f0.y + A1.w * f1.y;
        }
        if (j < je) {
            const int s0 = g_src[j];
            const float4 A0 = g_trigA[j];
            const float4 T0 = g_trigT[j];
            float2 f0 = *reinterpret_cast<const float2*>(x + (size_t)s0 * 64 + 2 * lane);
            if (lane >= 8) {
                float cr0 = (lane < 24) ? T0.x : T0.z, sr0 = (lane < 24) ? T0.y : T0.w;
                float a0 = cr0 * f0.x - sr0 * f0.y, b0 = sr0 * f0.x + cr0 * f0.y;
                f0.x = a0; f0.y = b0;
            }
            S[0].x += f0.x;        S[0].y += f0.y;
            S[1].x += A0.x * f0.x; S[1].y += A0.x * f0.y;
            S[2].x += A0.y * f0.x; S[2].y += A0.y * f0.y;
            S[3].x += A0.z * f0.x; S[3].y += A0.z * f0.y;
            S[4].x += A0.w * f0.x; S[4].y += A0.w * f0.y;
        }

        float* row = g_S + (size_t)v * 384;
#pragma unroll
        for (int b = 0; b < 5; ++b)
            *reinterpret_cast<float2*>(row + b * 64 + 2 * lane) = S[b];
        float2 xv = *reinterpret_cast<const float2*>(x + (size_t)v * 64 + 2 * lane);
        *reinterpret_cast<float2*>(row + 320 + 2 * lane) = xv;
    }
}

// ---------------- GEMM (50k x 384)@(384 x 64) + LN + nonlin + residual ----------------
// 128-row tile per CTA, 8 warps; warp wid owns output cols 8*wid..8*wid+7.
// 3-product bf16 split (ah*bh + ah*bl + al*bh). W fragments live in registers.
#define AP 196   /* smem pair stride (== 4 mod 32 -> conflict-free frag loads) */

__global__ __launch_bounds__(256) void gemm_kernel(
    const float* __restrict__ Wn,
    const float* __restrict__ Ks,
    const float* __restrict__ gamma,
    const float* __restrict__ beta,
    float* __restrict__ out)
{
    extern __shared__ uint32_t sm[];
    uint32_t* smh = sm;                    // hi: [128][AP]
    uint32_t* sml = sm + 128 * AP;         // lo: [128][AP]  (aliased by msg later)

    const int tid  = threadIdx.x;
    const int lane = tid & 31;
    const int wid  = tid >> 5;
    const int g    = lane >> 2;
    const int t    = lane & 3;
    const int v0   = blockIdx.x * 128;

    // ---- B fragments (hi/lo) in registers ----
    uint32_t bh[24][2], bl[24][2];
    {
        const int ocol = 8 * wid + g;
#pragma unroll
        for (int ks = 0; ks < 24; ++ks)
#pragma unroll
            for (int r = 0; r < 2; ++r) {
                const int k0 = 16 * ks + 8 * r;     // compile-time per (ks,r)
                const float* wp = (k0 < 320)
                    ? (Wn + (k0 >> 6) * 4096 + ocol * 64 + (k0 & 63) + 2 * t)
                    : (Ks + ocol * 64 + (k0 - 320) + 2 * t);
                const float2 w = *reinterpret_cast<const float2*>(wp);
                uint32_t hi = pack_bf16(w.x, w.y);
                float h0 = __uint_as_float(hi << 16);
                float h1 = __uint_as_float(hi & 0xffff0000u);
                bh[ks][r] = hi;
                bl[ks][r] = pack_bf16(w.x - h0, w.y - h1);
            }
    }

    // ---- producer: S rows -> smem bf16 hi/lo ----
    for (int idx = tid; idx < 128 * 192; idx += 256) {
        const int row = idx / 192;
        const int p   = idx - row * 192;
        const int v   = v0 + row;
        float2 w = (v < V_N)
            ? *reinterpret_cast<const float2*>(g_S + (size_t)v * 384 + 2 * p)
            : make_float2(0.f, 0.f);
        uint32_t hi = pack_bf16(w.x, w.y);
        float h0 = __uint_as_float(hi << 16);
        float h1 = __uint_as_float(hi & 0xffff0000u);
        smh[row * AP + p] = hi;
        sml[row * AP + p] = pack_bf16(w.x - h0, w.y - h1);
    }
    __syncthreads();

    // ---- MMA ----
    float acc[8][4];
#pragma unroll
    for (int m = 0; m < 8; ++m)
        acc[m][0] = acc[m][1] = acc[m][2] = acc[m][3] = 0.f;

#pragma unroll
    for (int ks = 0; ks < 24; ++ks) {
#pragma unroll
        for (int m = 0; m < 8; ++m) {
            const int row = m * 16 + g;
            const int c   = 8 * ks + t;
            uint32_t ah[4], al[4];
            ah[0] = smh[row * AP + c];
            ah[1] = smh[(row + 8) * AP + c];
            ah[2] = smh[row * AP + c + 4];
            ah[3] = smh[(row + 8) * AP + c + 4];
            al[0] = sml[row * AP + c];
            al[1] = sml[(row + 8) * AP + c];
            al[2] = sml[row * AP + c + 4];
            al[3] = sml[(row + 8) * AP + c + 4];
            mma_bf16(acc[m], ah, bh[ks]);
            mma_bf16(acc[m], ah, bl[ks]);
            mma_bf16(acc[m], al, bh[ks]);
        }
    }
    __syncthreads();               // everyone done reading sml before aliasing

    // ---- stage msg[128][68] (aliases sml) ----
    float* msg = reinterpret_cast<float*>(sml);
    {
        const int col = 8 * wid + 2 * t;
#pragma unroll
        for (int m = 0; m < 8; ++m) {
            const int row = m * 16 + g;
            *reinterpret_cast<float2*>(&msg[row * 68 + col])       = make_float2(acc[m][0], acc[m][1]);
            *reinterpret_cast<float2*>(&msg[(row + 8) * 68 + col]) = make_float2(acc[m][2], acc[m][3]);
        }
    }
    __syncthreads();

    // ---- epilogue: LN + nonlin + residual ----
    const float ga0 = gamma[2 * lane], ga1 = gamma[2 * lane + 1];
    const float be0 = beta[2 * lane],  be1 = beta[2 * lane + 1];

    for (int rr = 0; rr < 16; ++rr) {
        const int row = wid * 16 + rr;
        const int v   = v0 + row;
        if (v >= V_N) break;
        float2 h2 = *reinterpret_cast<const float2*>(&msg[row * 68 + 2 * lane]);
        float acc0 = h2.x, acc1 = h2.y;

        float sum = acc0 + acc1;
        float ssq = acc0 * acc0 + acc1 * acc1;
#pragma unroll
        for (int o = 16; o; o >>= 1) {
            sum += __shfl_xor_sync(0xffffffffu, sum, o);
            ssq += __shfl_xor_sync(0xffffffffu, ssq, o);
        }
        float mu  = sum * (1.f / 64.f);
        float var = ssq * (1.f / 64.f) - mu * mu;
        float rs  = rsqrtf(var + 1e-5f);
        float h0  = (acc0 - mu) * rs * ga0 + be0;
        float h1  = (acc1 - mu) * rs * ga1 + be1;

        if (lane < 8) {
            h0 = fmaxf(h0, 0.f);
            h1 = fmaxf(h1, 0.f);
        } else {
            float n  = sqrtf(h0 * h0 + h1 * h1);
            n        = fmaxf(n, 1e-8f);
            float sp = (n > 20.f) ? n : log1pf(expf(n));
            float sc = sp / n;
            h0 *= sc;
            h1 *= sc;
        }

        // exact residual from the f32 x copy appended to the S row
        float2 xv = *reinterpret_cast<const float2*>(g_S + (size_t)v * 384 + 320 + 2 * lane);
        *reinterpret_cast<float2*>(out + (size_t)v * 64 + 2 * lane) =
            make_float2(h0 + xv.x, h1 + xv.y);
    }
}

extern "C" void kernel_launch(void* const* d_in, const int* in_sizes, int n_in,
                              void* d_out, int out_size)
{
    const float* x      = (const float*)d_in[0];
    const int*   ei     = (const int*)  d_in[1];
    const float* angles = (const float*)d_in[2];
    const float* trans  = (const float*)d_in[3];
    const float* K_self = (const float*)d_in[4];
    const float* Wn     = (const float*)d_in[5];
    const float* gamma  = (const float*)d_in[6];
    const float* beta   = (const float*)d_in[7];
    float* out = (float*)d_out;

    (void)in_sizes; (void)n_in; (void)out_size;

    zero_hist_kernel<<<(V_N + 255) / 256, 256>>>();
    hist_kernel<<<(E_N + 255) / 256, 256>>>(ei);
    scan_kernel<<<1, 256>>>();
    scatter_kernel<<<(E_N + 255) / 256, 256>>>(ei, angles, trans);
    accum_kernel<<<296, 256>>>(x);

    {
        const int shbytes = 2 * 128 * AP * 4;   // 200704
        cudaFuncSetAttribute(gemm_kernel,
                             cudaFuncAttributeMaxDynamicSharedMemorySize, shbytes);
        gemm_kernel<<<(V_N + 127) / 128, 256, shbytes>>>(Wn, K_self, gamma, beta, out);
    }
}

// round 5
// speedup vs baseline: 1.4290x; 1.4290x over previous
#include <cuda_runtime.h>
#include <math.h>
#include <stdint.h>

#define V_N 50000
#define E_N 800000
#define SCAN_B 196          /* 196*256 = 50176 >= V_N */

__device__ int    g_hist[SCAN_B * 256];
__device__ int    g_start[V_N + 1];
__device__ int    g_cursor[V_N];
__device__ int    g_bsum[256];
__device__ int    g_boff[256];
__device__ int    g_src[E_N];
__device__ float4 g_trigA[E_N];   // (cos a, sin a, cos 2a, sin 2a)
__device__ float4 g_trigT[E_N];   // (cos t, sin t, cos 2t, sin 2t)
__device__ float  g_S[(size_t)V_N * 320];

// ---------------- helpers ----------------
__device__ __forceinline__ uint32_t pack_bf16(float e0, float e1) {
    uint32_t r;
    asm("cvt.rn.bf16x2.f32 %0, %1, %2;" : "=r"(r) : "f"(e1), "f"(e0));
    return r;
}

__device__ __forceinline__ void mma_bf16(float* d, const uint32_t* a, const uint32_t* b) {
    asm volatile(
        "mma.sync.aligned.m16n8k16.row.col.f32.bf16.bf16.f32 "
        "{%0,%1,%2,%3}, {%4,%5,%6,%7}, {%8,%9}, {%0,%1,%2,%3};"
        : "+f"(d[0]), "+f"(d[1]), "+f"(d[2]), "+f"(d[3])
        : "r"(a[0]), "r"(a[1]), "r"(a[2]), "r"(a[3]), "r"(b[0]), "r"(b[1]));
}

// ---------------- sort pipeline (all coalesced) ----------------
__global__ void zero_hist_kernel() {
    int i = blockIdx.x * blockDim.x + threadIdx.x;
    if (i < SCAN_B * 256) g_hist[i] = 0;
}

__global__ void hist_kernel(const int* __restrict__ ei) {
    int e = blockIdx.x * blockDim.x + threadIdx.x;
    if (e < E_N) atomicAdd(&g_hist[ei[E_N + e]], 1);
}

__global__ void s1_blocksum_kernel() {
    __shared__ int sh[256];
    const int t = threadIdx.x, idx = blockIdx.x * 256 + t;
    sh[t] = g_hist[idx];
    __syncthreads();
    for (int o = 128; o; o >>= 1) {
        if (t < o) sh[t] += sh[t + o];
        __syncthreads();
    }
    if (t == 0) g_bsum[blockIdx.x] = sh[0];
}

__global__ void s2_scanbsum_kernel() {
    __shared__ int sh[256];
    const int t = threadIdx.x;
    const int v = (t < SCAN_B) ? g_bsum[t] : 0;
    sh[t] = v;
    __syncthreads();
    for (int o = 1; o < 256; o <<= 1) {
        int u = (t >= o) ? sh[t - o] : 0;
        __syncthreads();
        sh[t] += u;
        __syncthreads();
    }
    g_boff[t] = sh[t] - v;   // exclusive prefix of block sums
}

__global__ void s3_expand_kernel() {
    __shared__ int sh[256];
    const int t = threadIdx.x, idx = blockIdx.x * 256 + t;
    const int v = g_hist[idx];
    sh[t] = v;
    __syncthreads();
    for (int o = 1; o < 256; o <<= 1) {
        int u = (t >= o) ? sh[t - o] : 0;
        __syncthreads();
        sh[t] += u;
        __syncthreads();
    }
    const int excl = sh[t] - v + g_boff[blockIdx.x];
    if (idx < V_N) {
        g_start[idx]  = excl;
        g_cursor[idx] = excl;
        if (idx == V_N - 1) g_start[V_N] = excl + v;
    }
}

__global__ void scatter_kernel(const int* __restrict__ ei,
                               const float* __restrict__ angles,
                               const float* __restrict__ trans) {
    int e = blockIdx.x * blockDim.x + threadIdx.x;
    if (e >= E_N) return;
    int tgt = ei[E_N + e];
    int pos = atomicAdd(&g_cursor[tgt], 1);
    g_src[pos] = ei[e];
    float sa, ca, st, ct;
    __sincosf(angles[e], &sa, &ca);
    __sincosf(trans[e],  &st, &ct);
    g_trigA[pos] = make_float4(ca, sa, fmaf(2.f * ca, ca, -1.f), 2.f * sa * ca);
    g_trigT[pos] = make_float4(ct, st, fmaf(2.f * ct, ct, -1.f), 2.f * st * ct);
}

// ---------------- per-vertex S accumulation ----------------
// One warp per vertex; lane l owns channels (2l, 2l+1):
// lanes 0..7 scalars, 8..23 order-1 pairs, 24..31 order-2 pairs.
__global__ __launch_bounds__(256) void accum_kernel(const float* __restrict__ x) {
    const int lane = threadIdx.x & 31;
    const int gw   = (blockIdx.x * blockDim.x + threadIdx.x) >> 5;
    const int nw   = (gridDim.x * blockDim.x) >> 5;

    for (int v = gw; v < V_N; v += nw) {
        const int jb = g_start[v];
        const int je = g_start[v + 1];
        float2 S[5];
#pragma unroll
        for (int b = 0; b < 5; ++b) S[b] = make_float2(0.f, 0.f);

        int j = jb;
        for (; j + 2 <= je; j += 2) {
            const int s0 = g_src[j], s1 = g_src[j + 1];
            const float4 A0 = g_trigA[j], A1 = g_trigA[j + 1];
            const float4 T0 = g_trigT[j], T1 = g_trigT[j + 1];
            float2 f0 = *reinterpret_cast<const float2*>(x + (size_t)s0 * 64 + 2 * lane);
            float2 f1 = *reinterpret_cast<const float2*>(x + (size_t)s1 * 64 + 2 * lane);
            if (lane >= 8) {
                float cr0 = (lane < 24) ? T0.x : T0.z, sr0 = (lane < 24) ? T0.y : T0.w;
                float cr1 = (lane < 24) ? T1.x : T1.z, sr1 = (lane < 24) ? T1.y : T1.w;
                float a0 = cr0 * f0.x - sr0 * f0.y, b0 = sr0 * f0.x + cr0 * f0.y;
                float a1 = cr1 * f1.x - sr1 * f1.y, b1 = sr1 * f1.x + cr1 * f1.y;
                f0.x = a0; f0.y = b0; f1.x = a1; f1.y = b1;
            }
            S[0].x += f0.x + f1.x;                S[0].y += f0.y + f1.y;
            S[1].x += A0.x * f0.x + A1.x * f1.x;  S[1].y += A0.x * f0.y + A1.x * f1.y;
            S[2].x += A0.y * f0.x + A1.y * f1.x;  S[2].y += A0.y * f0.y + A1.y * f1.y;
            S[3].x += A0.z * f0.x + A1.z * f1.x;  S[3].y += A0.z * f0.y + A1.z * f1.y;
            S[4].x += A0.w * f0.x + A1.w * f1.x;  S[4].y += A0.w * f0.y + A1.w * f1.y;
        }
        if (j < je) {
            const int s0 = g_src[j];
            const float4 A0 = g_trigA[j];
            const float4 T0 = g_trigT[j];
            float2 f0 = *reinterpret_cast<const float2*>(x + (size_t)s0 * 64 + 2 * lane);
            if (lane >= 8) {
                float cr0 = (lane < 24) ? T0.x : T0.z, sr0 = (lane < 24) ? T0.y : T0.w;
                float a0 = cr0 * f0.x - sr0 * f0.y, b0 = sr0 * f0.x + cr0 * f0.y;
                f0.x = a0; f0.y = b0;
            }
            S[0].x += f0.x;        S[0].y += f0.y;
            S[1].x += A0.x * f0.x; S[1].y += A0.x * f0.y;
            S[2].x += A0.y * f0.x; S[2].y += A0.y * f0.y;
            S[3].x += A0.z * f0.x; S[3].y += A0.z * f0.y;
            S[4].x += A0.w * f0.x; S[4].y += A0.w * f0.y;
        }

        float* row = g_S + (size_t)v * 320;
#pragma unroll
        for (int b = 0; b < 5; ++b)
            *reinterpret_cast<float2*>(row + b * 64 + 2 * lane) = S[b];
    }
}

// ---------------- GEMM (50k x 384)@(384 x 64) + LN + nonlin + residual ----------------
// A row v = [S(320) | x(64)]; 128-row tile per CTA; warp wid owns out cols 8w..8w+7.
// 3-product bf16 split. W fragments resident in registers.
#define AP 196   /* smem pair stride (== 4 mod 32 -> conflict-free frag loads) */

__global__ __launch_bounds__(256) void gemm_kernel(
    const float* __restrict__ x,
    const float* __restrict__ Wn,
    const float* __restrict__ Ks,
    const float* __restrict__ gamma,
    const float* __restrict__ beta,
    float* __restrict__ out)
{
    extern __shared__ uint32_t sm[];
    uint32_t* smh = sm;                    // hi: [128][AP]
    uint32_t* sml = sm + 128 * AP;         // lo: [128][AP]  (aliased by msg later)

    const int tid  = threadIdx.x;
    const int lane = tid & 31;
    const int wid  = tid >> 5;
    const int g    = lane >> 2;
    const int t    = lane & 3;
    const int v0   = blockIdx.x * 128;

    // ---- B fragments (hi/lo) in registers ----
    uint32_t bh[24][2], bl[24][2];
    {
        const int ocol = 8 * wid + g;
#pragma unroll
        for (int ks = 0; ks < 24; ++ks)
#pragma unroll
            for (int r = 0; r < 2; ++r) {
                const int k0 = 16 * ks + 8 * r;
                const float* wp = (k0 < 320)
                    ? (Wn + (k0 >> 6) * 4096 + ocol * 64 + (k0 & 63) + 2 * t)
                    : (Ks + ocol * 64 + (k0 - 320) + 2 * t);
                const float2 w = *reinterpret_cast<const float2*>(wp);
                uint32_t hi = pack_bf16(w.x, w.y);
                float h0 = __uint_as_float(hi << 16);
                float h1 = __uint_as_float(hi & 0xffff0000u);
                bh[ks][r] = hi;
                bl[ks][r] = pack_bf16(w.x - h0, w.y - h1);
            }
    }

    // ---- producer: [S | x] rows -> smem bf16 hi/lo ----
    for (int idx = tid; idx < 128 * 192; idx += 256) {
        const int row = idx / 192;
        const int p   = idx - row * 192;
        const int v   = v0 + row;
        float2 w = make_float2(0.f, 0.f);
        if (v < V_N) {
            w = (p < 160)
                ? *reinterpret_cast<const float2*>(g_S + (size_t)v * 320 + 2 * p)
                : *reinterpret_cast<const float2*>(x + (size_t)v * 64 + 2 * (p - 160));
        }
        uint32_t hi = pack_bf16(w.x, w.y);
        float h0 = __uint_as_float(hi << 16);
        float h1 = __uint_as_float(hi & 0xffff0000u);
        smh[row * AP + p] = hi;
        sml[row * AP + p] = pack_bf16(w.x - h0, w.y - h1);
    }
    __syncthreads();

    // ---- MMA ----
    float acc[8][4];
#pragma unroll
    for (int m = 0; m < 8; ++m)
        acc[m][0] = acc[m][1] = acc[m][2] = acc[m][3] = 0.f;

#pragma unroll
    for (int ks = 0; ks < 24; ++ks) {
#pragma unroll
        for (int m = 0; m < 8; ++m) {
            const int row = m * 16 + g;
            const int c   = 8 * ks + t;
            uint32_t ah[4], al[4];
            ah[0] = smh[row * AP + c];
            ah[1] = smh[(row + 8) * AP + c];
            ah[2] = smh[row * AP + c + 4];
            ah[3] = smh[(row + 8) * AP + c + 4];
            al[0] = sml[row * AP + c];
            al[1] = sml[(row + 8) * AP + c];
            al[2] = sml[row * AP + c + 4];
            al[3] = sml[(row + 8) * AP + c + 4];
            mma_bf16(acc[m], ah, bh[ks]);
            mma_bf16(acc[m], ah, bl[ks]);
            mma_bf16(acc[m], al, bh[ks]);
        }
    }
    __syncthreads();

    // ---- stage msg[128][68] (aliases sml) ----
    float* msg = reinterpret_cast<float*>(sml);
    {
        const int col = 8 * wid + 2 * t;
#pragma unroll
        for (int m = 0; m < 8; ++m) {
            const int row = m * 16 + g;
            *reinterpret_cast<float2*>(&msg[row * 68 + col])       = make_float2(acc[m][0], acc[m][1]);
            *reinterpret_cast<float2*>(&msg[(row + 8) * 68 + col]) = make_float2(acc[m][2], acc[m][3]);
        }
    }
    __syncthreads();

    // ---- epilogue: LN + nonlin + residual (x read direct, exact f32) ----
    const float ga0 = gamma[2 * lane], ga1 = gamma[2 * lane + 1];
    const float be0 = beta[2 * lane],  be1 = beta[2 * lane + 1];

    for (int rr = 0; rr < 16; ++rr) {
        const int row = wid * 16 + rr;
        const int v   = v0 + row;
        if (v >= V_N) break;
        float2 h2 = *reinterpret_cast<const float2*>(&msg[row * 68 + 2 * lane]);
        float acc0 = h2.x, acc1 = h2.y;

        float sum = acc0 + acc1;
        float ssq = acc0 * acc0 + acc1 * acc1;
#pragma unroll
        for (int o = 16; o; o >>= 1) {
            sum += __shfl_xor_sync(0xffffffffu, sum, o);
            ssq += __shfl_xor_sync(0xffffffffu, ssq, o);
        }
        float mu  = sum * (1.f / 64.f);
        float var = ssq * (1.f / 64.f) - mu * mu;
        float rs  = rsqrtf(var + 1e-5f);
        float h0  = (acc0 - mu) * rs * ga0 + be0;
        float h1  = (acc1 - mu) * rs * ga1 + be1;

        if (lane < 8) {
            h0 = fmaxf(h0, 0.f);
            h1 = fmaxf(h1, 0.f);
        } else {
            float n  = sqrtf(h0 * h0 + h1 * h1);
            n        = fmaxf(n, 1e-8f);
            float sp = (n > 20.f) ? n : log1pf(expf(n));
            float sc = sp / n;
            h0 *= sc;
            h1 *= sc;
        }

        float2 xv = *reinterpret_cast<const float2*>(x + (size_t)v * 64 + 2 * lane);
        *reinterpret_cast<float2*>(out + (size_t)v * 64 + 2 * lane) =
            make_float2(h0 + xv.x, h1 + xv.y);
    }
}

extern "C" void kernel_launch(void* const* d_in, const int* in_sizes, int n_in,
                              void* d_out, int out_size)
{
    const float* x      = (const float*)d_in[0];
    const int*   ei     = (const int*)  d_in[1];
    const float* angles = (const float*)d_in[2];
    const float* trans  = (const float*)d_in[3];
    const float* K_self = (const float*)d_in[4];
    const float* Wn     = (const float*)d_in[5];
    const float* gamma  = (const float*)d_in[6];
    const float* beta   = (const float*)d_in[7];
    float* out = (float*)d_out;

    (void)in_sizes; (void)n_in; (void)out_size;

    zero_hist_kernel<<<SCAN_B, 256>>>();
    hist_kernel<<<(E_N + 255) / 256, 256>>>(ei);
    s1_blocksum_kernel<<<SCAN_B, 256>>>();
    s2_scanbsum_kernel<<<1, 256>>>();
    s3_expand_kernel<<<SCAN_B, 256>>>();
    scatter_kernel<<<(E_N + 255) / 256, 256>>>(ei, angles, trans);
    accum_kernel<<<444, 256>>>(x);

    {
        const int shbytes = 2 * 128 * AP * 4;   // 200704
        cudaFuncSetAttribute(gemm_kernel,
                             cudaFuncAttributeMaxDynamicSharedMemorySize, shbytes);
        gemm_kernel<<<(V_N + 127) / 128, 256, shbytes>>>(x, Wn, K_self, gamma, beta, out);
    }
}

// round 6
// speedup vs baseline: 1.6138x; 1.1293x over previous
#include <cuda_runtime.h>
#include <math.h>
#include <stdint.h>

#define V_N 50000
#define E_N 800000
#define SCAN_B 196          /* 196*256 = 50176 >= V_N */

__device__ int    g_hist[SCAN_B * 256];
__device__ int    g_start[V_N + 1];
__device__ int    g_cursor[V_N];
__device__ int    g_bsum[256];
__device__ int    g_boff[256];
__device__ int    g_src[E_N];
__device__ float4 g_trig[(size_t)E_N * 2];   // [2e]=(ca,sa,c2a,s2a), [2e+1]=(ct,st,c2t,s2t)
__device__ float  g_S[(size_t)V_N * 320];

// ---------------- helpers ----------------
__device__ __forceinline__ uint32_t pack_bf16(float e0, float e1) {
    uint32_t r;
    asm("cvt.rn.bf16x2.f32 %0, %1, %2;" : "=r"(r) : "f"(e1), "f"(e0));
    return r;
}

__device__ __forceinline__ void mma_bf16(float* d, const uint32_t* a, const uint32_t* b) {
    asm volatile(
        "mma.sync.aligned.m16n8k16.row.col.f32.bf16.bf16.f32 "
        "{%0,%1,%2,%3}, {%4,%5,%6,%7}, {%8,%9}, {%0,%1,%2,%3};"
        : "+f"(d[0]), "+f"(d[1]), "+f"(d[2]), "+f"(d[3])
        : "r"(a[0]), "r"(a[1]), "r"(a[2]), "r"(a[3]), "r"(b[0]), "r"(b[1]));
}

// ---------------- sort pipeline (all coalesced) ----------------
__global__ void zero_hist_kernel() {
    int i = blockIdx.x * blockDim.x + threadIdx.x;
    if (i < SCAN_B * 256) g_hist[i] = 0;
}

__global__ void hist_kernel(const int* __restrict__ ei) {
    int e = blockIdx.x * blockDim.x + threadIdx.x;
    if (e < E_N) atomicAdd(&g_hist[ei[E_N + e]], 1);
}

__global__ void s1_blocksum_kernel() {
    __shared__ int sh[256];
    const int t = threadIdx.x, idx = blockIdx.x * 256 + t;
    sh[t] = g_hist[idx];
    __syncthreads();
    for (int o = 128; o; o >>= 1) {
        if (t < o) sh[t] += sh[t + o];
        __syncthreads();
    }
    if (t == 0) g_bsum[blockIdx.x] = sh[0];
}

__global__ void s2_scanbsum_kernel() {
    __shared__ int sh[256];
    const int t = threadIdx.x;
    const int v = (t < SCAN_B) ? g_bsum[t] : 0;
    sh[t] = v;
    __syncthreads();
    for (int o = 1; o < 256; o <<= 1) {
        int u = (t >= o) ? sh[t - o] : 0;
        __syncthreads();
        sh[t] += u;
        __syncthreads();
    }
    g_boff[t] = sh[t] - v;
}

__global__ void s3_expand_kernel() {
    __shared__ int sh[256];
    const int t = threadIdx.x, idx = blockIdx.x * 256 + t;
    const int v = g_hist[idx];
    sh[t] = v;
    __syncthreads();
    for (int o = 1; o < 256; o <<= 1) {
        int u = (t >= o) ? sh[t - o] : 0;
        __syncthreads();
        sh[t] += u;
        __syncthreads();
    }
    const int excl = sh[t] - v + g_boff[blockIdx.x];
    if (idx < V_N) {
        g_start[idx]  = excl;
        g_cursor[idx] = excl;
        if (idx == V_N - 1) g_start[V_N] = excl + v;
    }
}

__global__ void scatter_kernel(const int* __restrict__ ei,
                               const float* __restrict__ angles,
                               const float* __restrict__ trans) {
    int e = blockIdx.x * blockDim.x + threadIdx.x;
    if (e >= E_N) return;
    int tgt = ei[E_N + e];
    int pos = atomicAdd(&g_cursor[tgt], 1);
    g_src[pos] = ei[e];
    float sa, ca, st, ct;
    __sincosf(angles[e], &sa, &ca);
    __sincosf(trans[e],  &st, &ct);
    g_trig[2 * pos]     = make_float4(ca, sa, fmaf(2.f * ca, ca, -1.f), 2.f * sa * ca);
    g_trig[2 * pos + 1] = make_float4(ct, st, fmaf(2.f * ct, ct, -1.f), 2.f * st * ct);
}

// ---------------- per-vertex S accumulation ----------------
// One warp per vertex; half-warp per edge; lane owns 4 channels via float4.
// l = lane&15: l<4 -> scalars (ch 0..15); 4<=l<12 -> order-1 (16..47); l>=12 -> order-2.
__global__ __launch_bounds__(256) void accum_kernel(const float* __restrict__ x) {
    const int lane = threadIdx.x & 31;
    const int h    = lane >> 4;
    const int l    = lane & 15;
    const int gw   = (blockIdx.x * blockDim.x + threadIdx.x) >> 5;
    const int nw   = (gridDim.x * blockDim.x) >> 5;

    for (int v = gw; v < V_N; v += nw) {
        const int jb = g_start[v];
        const int je = g_start[v + 1];

        float4 S0 = make_float4(0.f, 0.f, 0.f, 0.f);
        float4 S1 = S0, S2 = S0, S3 = S0, S4 = S0;

        for (int j = jb + h; j < je; j += 2) {
            const int    src = g_src[j];
            const float4 A   = g_trig[2 * j];
            const float4 T   = g_trig[2 * j + 1];
            float4 f = *reinterpret_cast<const float4*>(x + (size_t)src * 64 + 4 * l);
            if (l >= 4) {
                const float cr = (l < 12) ? T.x : T.z;
                const float sr = (l < 12) ? T.y : T.w;
                const float a0 = cr * f.x - sr * f.y, b0 = sr * f.x + cr * f.y;
                const float a1 = cr * f.z - sr * f.w, b1 = sr * f.z + cr * f.w;
                f = make_float4(a0, b0, a1, b1);
            }
            S0.x += f.x;  S0.y += f.y;  S0.z += f.z;  S0.w += f.w;
            S1.x = fmaf(A.x, f.x, S1.x); S1.y = fmaf(A.x, f.y, S1.y);
            S1.z = fmaf(A.x, f.z, S1.z); S1.w = fmaf(A.x, f.w, S1.w);
            S2.x = fmaf(A.y, f.x, S2.x); S2.y = fmaf(A.y, f.y, S2.y);
            S2.z = fmaf(A.y, f.z, S2.z); S2.w = fmaf(A.y, f.w, S2.w);
            S3.x = fmaf(A.z, f.x, S3.x); S3.y = fmaf(A.z, f.y, S3.y);
            S3.z = fmaf(A.z, f.z, S3.z); S3.w = fmaf(A.z, f.w, S3.w);
            S4.x = fmaf(A.w, f.x, S4.x); S4.y = fmaf(A.w, f.y, S4.y);
            S4.z = fmaf(A.w, f.z, S4.z); S4.w = fmaf(A.w, f.w, S4.w);
        }

        // merge the two halves
#pragma unroll
        for (int c = 0; c < 1; ++c) {
            S0.x += __shfl_xor_sync(0xffffffffu, S0.x, 16);
            S0.y += __shfl_xor_sync(0xffffffffu, S0.y, 16);
            S0.z += __shfl_xor_sync(0xffffffffu, S0.z, 16);
            S0.w += __shfl_xor_sync(0xffffffffu, S0.w, 16);
            S1.x += __shfl_xor_sync(0xffffffffu, S1.x, 16);
            S1.y += __shfl_xor_sync(0xffffffffu, S1.y, 16);
            S1.z += __shfl_xor_sync(0xffffffffu, S1.z, 16);
            S1.w += __shfl_xor_sync(0xffffffffu, S1.w, 16);
            S2.x += __shfl_xor_sync(0xffffffffu, S2.x, 16);
            S2.y += __shfl_xor_sync(0xffffffffu, S2.y, 16);
            S2.z += __shfl_xor_sync(0xffffffffu, S2.z, 16);
            S2.w += __shfl_xor_sync(0xffffffffu, S2.w, 16);
            S3.x += __shfl_xor_sync(0xffffffffu, S3.x, 16);
            S3.y += __shfl_xor_sync(0xffffffffu, S3.y, 16);
            S3.z += __shfl_xor_sync(0xffffffffu, S3.z, 16);
            S3.w += __shfl_xor_sync(0xffffffffu, S3.w, 16);
            S4.x += __shfl_xor_sync(0xffffffffu, S4.x, 16);
            S4.y += __shfl_xor_sync(0xffffffffu, S4.y, 16);
            S4.z += __shfl_xor_sync(0xffffffffu, S4.z, 16);
            S4.w += __shfl_xor_sync(0xffffffffu, S4.w, 16);
        }

        if (h == 0) {
            float* row = g_S + (size_t)v * 320 + 4 * l;
            *reinterpret_cast<float4*>(row)       = S0;
            *reinterpret_cast<float4*>(row + 64)  = S1;
            *reinterpret_cast<float4*>(row + 128) = S2;
            *reinterpret_cast<float4*>(row + 192) = S3;
            *reinterpret_cast<float4*>(row + 256) = S4;
        }
    }
}

// ---------------- GEMM (50k x 384)@(384 x 64) + LN + nonlin + residual ----------------
#define AP 196

__global__ __launch_bounds__(256) void gemm_kernel(
    const float* __restrict__ x,
    const float* __restrict__ Wn,
    const float* __restrict__ Ks,
    const float* __restrict__ gamma,
    const float* __restrict__ beta,
    float* __restrict__ out)
{
    extern __shared__ uint32_t sm[];
    uint32_t* smh = sm;
    uint32_t* sml = sm + 128 * AP;

    const int tid  = threadIdx.x;
    const int lane = tid & 31;
    const int wid  = tid >> 5;
    const int g    = lane >> 2;
    const int t    = lane & 3;
    const int v0   = blockIdx.x * 128;

    uint32_t bh[24][2], bl[24][2];
    {
        const int ocol = 8 * wid + g;
#pragma unroll
        for (int ks = 0; ks < 24; ++ks)
#pragma unroll
            for (int r = 0; r < 2; ++r) {
                const int k0 = 16 * ks + 8 * r;
                const float* wp = (k0 < 320)
                    ? (Wn + (k0 >> 6) * 4096 + ocol * 64 + (k0 & 63) + 2 * t)
                    : (Ks + ocol * 64 + (k0 - 320) + 2 * t);
                const float2 w = *reinterpret_cast<const float2*>(wp);
                uint32_t hi = pack_bf16(w.x, w.y);
                float h0 = __uint_as_float(hi << 16);
                float h1 = __uint_as_float(hi & 0xffff0000u);
                bh[ks][r] = hi;
                bl[ks][r] = pack_bf16(w.x - h0, w.y - h1);
            }
    }

    for (int idx = tid; idx < 128 * 192; idx += 256) {
        const int row = idx / 192;
        const int p   = idx - row * 192;
        const int v   = v0 + row;
        float2 w = make_float2(0.f, 0.f);
        if (v < V_N) {
            w = (p < 160)
                ? *reinterpret_cast<const float2*>(g_S + (size_t)v * 320 + 2 * p)
                : *reinterpret_cast<const float2*>(x + (size_t)v * 64 + 2 * (p - 160));
        }
        uint32_t hi = pack_bf16(w.x, w.y);
        float h0 = __uint_as_float(hi << 16);
        float h1 = __uint_as_float(hi & 0xffff0000u);
        smh[row * AP + p] = hi;
        sml[row * AP + p] = pack_bf16(w.x - h0, w.y - h1);
    }
    __syncthreads();

    float acc[8][4];
#pragma unroll
    for (int m = 0; m < 8; ++m)
        acc[m][0] = acc[m][1] = acc[m][2] = acc[m][3] = 0.f;

#pragma unroll
    for (int ks = 0; ks < 24; ++ks) {
#pragma unroll
        for (int m = 0; m < 8; ++m) {
            const int row = m * 16 + g;
            const int c   = 8 * ks + t;
            uint32_t ah[4], al[4];
            ah[0] = smh[row * AP + c];
            ah[1] = smh[(row + 8) * AP + c];
            ah[2] = smh[row * AP + c + 4];
            ah[3] = smh[(row + 8) * AP + c + 4];
            al[0] = sml[row * AP + c];
            al[1] = sml[(row + 8) * AP + c];
            al[2] = sml[row * AP + c + 4];
            al[3] = sml[(row + 8) * AP + c + 4];
            mma_bf16(acc[m], ah, bh[ks]);
            mma_bf16(acc[m], ah, bl[ks]);
            mma_bf16(acc[m], al, bh[ks]);
        }
    }
    __syncthreads();

    float* msg = reinterpret_cast<float*>(sml);
    {
        const int col = 8 * wid + 2 * t;
#pragma unroll
        for (int m = 0; m < 8; ++m) {
            const int row = m * 16 + g;
            *reinterpret_cast<float2*>(&msg[row * 68 + col])       = make_float2(acc[m][0], acc[m][1]);
            *reinterpret_cast<float2*>(&msg[(row + 8) * 68 + col]) = make_float2(acc[m][2], acc[m][3]);
        }
    }
    __syncthreads();

    const float ga0 = gamma[2 * lane], ga1 = gamma[2 * lane + 1];
    const float be0 = beta[2 * lane],  be1 = beta[2 * lane + 1];

    for (int rr = 0; rr < 16; ++rr) {
        const int row = wid * 16 + rr;
        const int v   = v0 + row;
        if (v >= V_N) break;
        float2 h2 = *reinterpret_cast<const float2*>(&msg[row * 68 + 2 * lane]);
        float acc0 = h2.x, acc1 = h2.y;

        float sum = acc0 + acc1;
        float ssq = acc0 * acc0 + acc1 * acc1;
#pragma unroll
        for (int o = 16; o; o >>= 1) {
            sum += __shfl_xor_sync(0xffffffffu, sum, o);
            ssq += __shfl_xor_sync(0xffffffffu, ssq, o);
        }
        float mu  = sum * (1.f / 64.f);
        float var = ssq * (1.f / 64.f) - mu * mu;
        float rs  = rsqrtf(var + 1e-5f);
        float h0  = (acc0 - mu) * rs * ga0 + be0;
        float h1  = (acc1 - mu) * rs * ga1 + be1;

        if (lane < 8) {
            h0 = fmaxf(h0, 0.f);
            h1 = fmaxf(h1, 0.f);
        } else {
            float n  = sqrtf(h0 * h0 + h1 * h1);
            n        = fmaxf(n, 1e-8f);
            float sp = (n > 20.f) ? n : log1pf(expf(n));
            float sc = sp / n;
            h0 *= sc;
            h1 *= sc;
        }

        float2 xv = *reinterpret_cast<const float2*>(x + (size_t)v * 64 + 2 * lane);
        *reinterpret_cast<float2*>(out + (size_t)v * 64 + 2 * lane) =
            make_float2(h0 + xv.x, h1 + xv.y);
    }
}

extern "C" void kernel_launch(void* const* d_in, const int* in_sizes, int n_in,
                              void* d_out, int out_size)
{
    const float* x      = (const float*)d_in[0];
    const int*   ei     = (const int*)  d_in[1];
    const float* angles = (const float*)d_in[2];
    const float* trans  = (const float*)d_in[3];
    const float* K_self = (const float*)d_in[4];
    const float* Wn     = (const float*)d_in[5];
    const float* gamma  = (const float*)d_in[6];
    const float* beta   = (const float*)d_in[7];
    float* out = (float*)d_out;

    (void)in_sizes; (void)n_in; (void)out_size;

    zero_hist_kernel<<<SCAN_B, 256>>>();
    hist_kernel<<<(E_N + 255) / 256, 256>>>(ei);
    s1_blocksum_kernel<<<SCAN_B, 256>>>();
    s2_scanbsum_kernel<<<1, 256>>>();
    s3_expand_kernel<<<SCAN_B, 256>>>();
    scatter_kernel<<<(E_N + 255) / 256, 256>>>(ei, angles, trans);
    accum_kernel<<<592, 256>>>(x);

    {
        const int shbytes = 2 * 128 * AP * 4;   // 200704
        cudaFuncSetAttribute(gemm_kernel,
                             cudaFuncAttributeMaxDynamicSharedMemorySize, shbytes);
        gemm_kernel<<<(V_N + 127) / 128, 256, shbytes>>>(x, Wn, K_self, gamma, beta, out);
    }
}